// round 8
// baseline (speedup 1.0000x reference)
#include <cuda_runtime.h>
#include <math.h>
#include <float.h>

#define BB   16
#define NN   4096
#define KK   4096
#define NCHUNK 4
#define CHUNK  1024      // NN / NCHUNK
#define QQ   2           // queries per thread in argmin
#define IN1  16384
#define H1   1024
#define H2   512
#define OUTD 256

typedef unsigned long long ull;

#define FMA2(out, a, b, c) asm("fma.rn.f32x2 %0, %1, %2, %3;" : "=l"(out) : "l"(a), "l"(b), "l"(c))
#define MUL2(out, a, b)    asm("mul.rn.f32x2 %0, %1, %2;"     : "=l"(out) : "l"(a), "l"(b))
#define ADD2(out, a, b)    asm("add.rn.f32x2 %0, %1, %2;"     : "=l"(out) : "l"(a), "l"(b))

__device__ __forceinline__ ull pk2(float lo, float hi) {
    ull r; asm("mov.b64 %0, {%1, %2};" : "=l"(r) : "f"(lo), "f"(hi)); return r;
}
__device__ __forceinline__ void upk2(float& lo, float& hi, ull v) {
    asm("mov.b64 {%0, %1}, %2;" : "=f"(lo), "=f"(hi) : "l"(v));
}

// ---- scratch ----
__device__ __align__(16) float4 g_packA[BB * NN / 2];       // 512 KB
__device__ __align__(16) float4 g_packB[BB * NN / 2];       // 512 KB
__device__ __align__(16) float2 g_bi  [BB * KK * NCHUNK];   // (best, idx-bits)
__device__ __align__(16) float  g_part1[128 * BB * H1];     // 8 MB
__device__ __align__(16) float  g_tmp  [16 * BB * H1];      // 1 MB
__device__ __align__(16) float  g_h1[BB * H1];
__device__ __align__(16) float  g_part2[64 * BB * H2];
__device__ __align__(16) float  g_h2[BB * H2];
__device__ __align__(16) float  g_part3[16 * BB * OUTD];
__device__ float g_dummy[32];

// ---- slot-shift no-op (deterministic) ----
__global__ void k_nop() { if (threadIdx.x == 0) g_dummy[blockIdx.x] = 1.0f; }

// ============================================================
// Prep: pack (-2x,-2y) pairs and (-2z,pn) pairs once.
//   pn = rn(rn(x*x)+rn(y*y))+rn(z*z)  (reference order)
// ============================================================
__global__ void k_prep(const float* __restrict__ pc) {
    const int t = blockIdx.x * 256 + threadIdx.x;     // over BB*NN/2
    if (t >= BB * NN / 2) return;
    const float* p = pc + (size_t)t * 6;
    float x0 = p[0], y0 = p[1], z0 = p[2];
    float x1 = p[3], y1 = p[4], z1 = p[5];
    float pn0 = __fadd_rn(__fadd_rn(__fmul_rn(x0, x0), __fmul_rn(y0, y0)),
                          __fmul_rn(z0, z0));
    float pn1 = __fadd_rn(__fadd_rn(__fmul_rn(x1, x1), __fmul_rn(y1, y1)),
                          __fmul_rn(z1, z1));
    g_packA[t] = make_float4(-2.0f * x0, -2.0f * x1, -2.0f * y0, -2.0f * y1);
    g_packB[t] = make_float4(-2.0f * z0, -2.0f * z1, pn0, pn1);
}

// shared tiles for argmin
struct ArgminSmem {
    ulonglong2 spA[CHUNK / 2];
    ulonglong2 spB[CHUNK / 2];
};

// recompute scalar distances inside winning group, first index == best
__device__ __forceinline__ int resolve_group(const ArgminSmem* s, int bg, float best,
                                             float bx, float by, float bz, float bn) {
    int bi = 0;
    bool found = false;
    #pragma unroll
    for (int p = 0; p < 4; p++) {
        ulonglong2 qa = s->spA[4 * bg + p];
        ulonglong2 qb = s->spB[4 * bg + p];
        float m2x0, m2x1, m2y0, m2y1, m2z0, m2z1, pn0, pn1;
        upk2(m2x0, m2x1, qa.x);
        upk2(m2y0, m2y1, qa.y);
        upk2(m2z0, m2z1, qb.x);
        upk2(pn0,  pn1,  qb.y);
        float c0 = __fmaf_rn(bz, m2z0, __fmaf_rn(by, m2y0, __fmul_rn(bx, m2x0)));
        float d0 = __fadd_rn(c0, __fadd_rn(bn, pn0));
        float c1 = __fmaf_rn(bz, m2z1, __fmaf_rn(by, m2y1, __fmul_rn(bx, m2x1)));
        float d1 = __fadd_rn(c1, __fadd_rn(bn, pn1));
        if (!found && d0 == best) { bi = 8 * bg + 2 * p;     found = true; }
        if (!found && d1 == best) { bi = 8 * bg + 2 * p + 1; found = true; }
    }
    return bi;
}

// ============================================================
// Argmin: bit-exact reference arithmetic, 2 pts per f32x2 op,
// 2 queries/thread, group-of-8 deferred min, 128-thread blocks
// (single wave: 1024 blocks, ~8/SM capacity).
//   d = rn(fma(bz,-2z,fma(by,-2y,rn(bx*-2x))) + rn(bn+pn))
// grid: (KK/(128*QQ), NCHUNK, BB) = (16,4,16), block 128
// ============================================================
__global__ void __launch_bounds__(128) k_argmin(const float* __restrict__ basis) {
    __shared__ ArgminSmem s;
    const int b  = blockIdx.z;
    const int c  = blockIdx.y;
    const int n0 = c * CHUNK;

    {
        const float4* srcA = g_packA + (size_t)b * (NN / 2) + c * (CHUNK / 2);
        const float4* srcB = g_packB + (size_t)b * (NN / 2) + c * (CHUNK / 2);
        float4* dA = (float4*)s.spA;
        float4* dB = (float4*)s.spB;
        #pragma unroll
        for (int j = threadIdx.x; j < CHUNK / 2; j += 128) {
            dA[j] = srcA[j];
            dB[j] = srcB[j];
        }
    }
    __syncthreads();

    const int k1 = blockIdx.x * 128 + threadIdx.x;    // 0..2047
    const int k2 = k1 + KK / QQ;                      // +2048

    const float bx1 = basis[k1 * 3 + 0], by1 = basis[k1 * 3 + 1], bz1 = basis[k1 * 3 + 2];
    const float bx2 = basis[k2 * 3 + 0], by2 = basis[k2 * 3 + 1], bz2 = basis[k2 * 3 + 2];
    const float bn1 = __fadd_rn(__fadd_rn(__fmul_rn(bx1, bx1), __fmul_rn(by1, by1)),
                                __fmul_rn(bz1, bz1));
    const float bn2 = __fadd_rn(__fadd_rn(__fmul_rn(bx2, bx2), __fmul_rn(by2, by2)),
                                __fmul_rn(bz2, bz2));
    const ull bxp1 = pk2(bx1, bx1), byp1 = pk2(by1, by1), bzp1 = pk2(bz1, bz1), bnp1 = pk2(bn1, bn1);
    const ull bxp2 = pk2(bx2, bx2), byp2 = pk2(by2, by2), bzp2 = pk2(bz2, bz2), bnp2 = pk2(bn2, bn2);

    float best1 = FLT_MAX, best2 = FLT_MAX;
    int   bg1 = 0, bg2 = 0;

    #pragma unroll 2
    for (int g = 0; g < CHUNK / 8; g++) {
        ull e1[4], e2[4];
        #pragma unroll
        for (int p = 0; p < 4; p++) {
            ulonglong2 qa = s.spA[4 * g + p];
            ulonglong2 qb = s.spB[4 * g + p];
            ull cr, t;
            MUL2(cr, bxp1, qa.x); FMA2(cr, byp1, qa.y, cr); FMA2(cr, bzp1, qb.x, cr);
            ADD2(t, bnp1, qb.y);  ADD2(e1[p], cr, t);
            MUL2(cr, bxp2, qa.x); FMA2(cr, byp2, qa.y, cr); FMA2(cr, bzp2, qb.x, cr);
            ADD2(t, bnp2, qb.y);  ADD2(e2[p], cr, t);
        }
        {
            float a0, a1, b0, b1, c0, c1, d0, d1;
            upk2(a0, a1, e1[0]); upk2(b0, b1, e1[1]);
            upk2(c0, c1, e1[2]); upk2(d0, d1, e1[3]);
            float m8 = fminf(fminf(fminf(a0, a1), fminf(b0, b1)),
                             fminf(fminf(c0, c1), fminf(d0, d1)));
            bg1   = (m8 < best1) ? g : bg1;
            best1 = fminf(best1, m8);
        }
        {
            float a0, a1, b0, b1, c0, c1, d0, d1;
            upk2(a0, a1, e2[0]); upk2(b0, b1, e2[1]);
            upk2(c0, c1, e2[2]); upk2(d0, d1, e2[3]);
            float m8 = fminf(fminf(fminf(a0, a1), fminf(b0, b1)),
                             fminf(fminf(c0, c1), fminf(d0, d1)));
            bg2   = (m8 < best2) ? g : bg2;
            best2 = fminf(best2, m8);
        }
    }

    const int bi1 = resolve_group(&s, bg1, best1, bx1, by1, bz1, bn1);
    const int bi2 = resolve_group(&s, bg2, best2, bx2, by2, bz2, bn2);

    g_bi[(b * KK + k1) * NCHUNK + c] = make_float2(best1, __int_as_float(n0 + bi1));
    g_bi[(b * KK + k2) * NCHUNK + c] = make_float2(best2, __int_as_float(n0 + bi2));
}

// ============================================================
// Combine chunk partials (ascending order, strict <), gather,
// write bps row: [dists(4096) | deltas(3*4096)]
// ============================================================
__global__ void k_finish(const float* __restrict__ pc,
                         const float* __restrict__ basis,
                         float* __restrict__ out_bps) {
    const int t = blockIdx.x * blockDim.x + threadIdx.x;
    if (t >= BB * KK) return;
    const int b = t >> 12;
    const int k = t & (KK - 1);

    const float4* q = (const float4*)(g_bi + (size_t)t * NCHUNK);
    float4 v01 = q[0];
    float4 v23 = q[1];

    float best = v01.x;
    int   bi   = __float_as_int(v01.y);
    if (v01.z < best) { best = v01.z; bi = __float_as_int(v01.w); }
    if (v23.x < best) { best = v23.x; bi = __float_as_int(v23.y); }
    if (v23.z < best) { best = v23.z; bi = __float_as_int(v23.w); }

    const float* p = pc + ((size_t)b * NN + bi) * 3;
    const float dx = __fadd_rn(p[0], -basis[k * 3 + 0]);
    const float dy = __fadd_rn(p[1], -basis[k * 3 + 1]);
    const float dz = __fadd_rn(p[2], -basis[k * 3 + 2]);
    const float ss = __fadd_rn(__fadd_rn(__fmul_rn(dx, dx), __fmul_rn(dy, dy)),
                               __fmul_rn(dz, dz));
    const float dist = sqrtf(ss);

    float* row = out_bps + (size_t)b * IN1;
    row[k]              = dist;
    row[KK + 3 * k + 0] = dx;
    row[KK + 3 * k + 1] = dy;
    row[KK + 3 * k + 2] = dz;
}

// ============================================================
// Split-K GEMM, 2 cols/thread, f32x2 acc. grid (H/512, INsz/CI)
// ============================================================
template <int CI>
__global__ void k_gemm2c(const float* __restrict__ A,
                         const float* __restrict__ W,
                         float* __restrict__ part,
                         int INsz, int H) {
    __shared__ __align__(16) float sA[CI * 16];
    const int i0 = blockIdx.y * CI;

    for (int idx = threadIdx.x; idx < CI * 16; idx += 256) {
        const int m  = idx / CI;
        const int il = idx % CI;
        sA[il * 16 + m] = A[(size_t)m * INsz + i0 + il];
    }
    __syncthreads();

    const int j = blockIdx.x * 512 + threadIdx.x;
    ull acc[16];
    #pragma unroll
    for (int m = 0; m < 16; m++) acc[m] = 0ull;

    const float* wp = W + (size_t)i0 * H + j;
    #pragma unroll 4
    for (int il = 0; il < CI; il++) {
        const float wa = wp[0];
        const float wb = wp[256];
        wp += H;
        const ull wpa = pk2(wa, wa);
        const ull wpb = pk2(wb, wb);
        const ulonglong2* ap = (const ulonglong2*)(sA + il * 16);
        ulonglong2 a0 = ap[0], a1 = ap[1], a2 = ap[2], a3 = ap[3];
        FMA2(acc[0],  a0.x, wpa, acc[0]);
        FMA2(acc[1],  a0.y, wpa, acc[1]);
        FMA2(acc[2],  a1.x, wpa, acc[2]);
        FMA2(acc[3],  a1.y, wpa, acc[3]);
        FMA2(acc[4],  a2.x, wpa, acc[4]);
        FMA2(acc[5],  a2.y, wpa, acc[5]);
        FMA2(acc[6],  a3.x, wpa, acc[6]);
        FMA2(acc[7],  a3.y, wpa, acc[7]);
        FMA2(acc[8],  a0.x, wpb, acc[8]);
        FMA2(acc[9],  a0.y, wpb, acc[9]);
        FMA2(acc[10], a1.x, wpb, acc[10]);
        FMA2(acc[11], a1.y, wpb, acc[11]);
        FMA2(acc[12], a2.x, wpb, acc[12]);
        FMA2(acc[13], a2.y, wpb, acc[13]);
        FMA2(acc[14], a3.x, wpb, acc[14]);
        FMA2(acc[15], a3.y, wpb, acc[15]);
    }

    float* pp = part + ((size_t)blockIdx.y * 16) * H + j;
    #pragma unroll
    for (int t = 0; t < 8; t++) {
        float lo, hi;
        upk2(lo, hi, acc[t]);
        pp[(size_t)(2 * t)     * H] = lo;
        pp[(size_t)(2 * t + 1) * H] = hi;
        upk2(lo, hi, acc[8 + t]);
        pp[(size_t)(2 * t)     * H + 256] = lo;
        pp[(size_t)(2 * t + 1) * H + 256] = hi;
    }
}

// ============================================================
// Split-K GEMM, 1 col/thread (H=256 tail). grid (H/256, INsz/CI)
// ============================================================
template <int CI>
__global__ void k_gemm1c(const float* __restrict__ A,
                         const float* __restrict__ W,
                         float* __restrict__ part,
                         int INsz, int H) {
    __shared__ __align__(16) float sA[CI * 16];
    const int i0 = blockIdx.y * CI;

    for (int idx = threadIdx.x; idx < CI * 16; idx += 256) {
        const int m  = idx / CI;
        const int il = idx % CI;
        sA[il * 16 + m] = A[(size_t)m * INsz + i0 + il];
    }
    __syncthreads();

    const int j = blockIdx.x * 256 + threadIdx.x;
    ull acc[8];
    #pragma unroll
    for (int m = 0; m < 8; m++) acc[m] = 0ull;

    const float* wp = W + (size_t)i0 * H + j;
    #pragma unroll 4
    for (int il = 0; il < CI; il++) {
        const float w = *wp;
        wp += H;
        const ull wpk = pk2(w, w);
        const ulonglong2* ap = (const ulonglong2*)(sA + il * 16);
        ulonglong2 a0 = ap[0], a1 = ap[1], a2 = ap[2], a3 = ap[3];
        FMA2(acc[0], a0.x, wpk, acc[0]);
        FMA2(acc[1], a0.y, wpk, acc[1]);
        FMA2(acc[2], a1.x, wpk, acc[2]);
        FMA2(acc[3], a1.y, wpk, acc[3]);
        FMA2(acc[4], a2.x, wpk, acc[4]);
        FMA2(acc[5], a2.y, wpk, acc[5]);
        FMA2(acc[6], a3.x, wpk, acc[6]);
        FMA2(acc[7], a3.y, wpk, acc[7]);
    }

    float* pp = part + ((size_t)blockIdx.y * 16) * H + j;
    #pragma unroll
    for (int t = 0; t < 8; t++) {
        float lo, hi;
        upk2(lo, hi, acc[t]);
        pp[(size_t)(2 * t)     * H] = lo;
        pp[(size_t)(2 * t + 1) * H] = hi;
    }
}

// ============================================================
// Reduces with explicit load arrays (force MLP).
// Order of summation ascending -> deterministic.
// ============================================================
template <int P>
__global__ void __launch_bounds__(256) k_red_s1(const float4* __restrict__ part,
                                                float4* __restrict__ tmp,
                                                int total4) {
    const int t = blockIdx.x * 256 + threadIdx.x;
    const int group = t / total4;
    const int el    = t - group * total4;
    const float4* p = part + (size_t)group * P * total4 + el;
    float4 v[P];
    #pragma unroll
    for (int q = 0; q < P; q++) v[q] = p[(size_t)q * total4];
    float4 s = v[0];
    #pragma unroll
    for (int q = 1; q < P; q++) {
        s.x += v[q].x; s.y += v[q].y; s.z += v[q].z; s.w += v[q].w;
    }
    tmp[t] = s;
}

template <int NG>
__global__ void __launch_bounds__(256) k_red_s2(const float4* __restrict__ tmp,
                                                const float4* __restrict__ bias,
                                                float4* __restrict__ outv,
                                                int total4, int H4, int do_lrelu) {
    const int t = blockIdx.x * 256 + threadIdx.x;
    if (t >= total4) return;
    float4 v[NG];
    #pragma unroll
    for (int g = 0; g < NG; g++) v[g] = tmp[(size_t)g * total4 + t];
    float4 s = v[0];
    #pragma unroll
    for (int g = 1; g < NG; g++) {
        s.x += v[g].x; s.y += v[g].y; s.z += v[g].z; s.w += v[g].w;
    }
    float4 bv = bias[t & (H4 - 1)];
    s.x += bv.x; s.y += bv.y; s.z += bv.z; s.w += bv.w;
    if (do_lrelu) {
        if (s.x < 0.f) s.x *= 0.2f;
        if (s.y < 0.f) s.y *= 0.2f;
        if (s.z < 0.f) s.z *= 0.2f;
        if (s.w < 0.f) s.w *= 0.2f;
    }
    outv[t] = s;
}

// ============================================================
extern "C" void kernel_launch(void* const* d_in, const int* in_sizes, int n_in,
                              void* d_out, int out_size) {
    const float* pc    = (const float*)d_in[0];
    const float* basis = (const float*)d_in[1];
    const float* W1    = (const float*)d_in[2];
    const float* b1    = (const float*)d_in[3];
    const float* W2    = (const float*)d_in[4];
    const float* b2    = (const float*)d_in[5];
    const float* W3    = (const float*)d_in[6];
    const float* b3    = (const float*)d_in[7];

    float* out = (float*)d_out;            // global_feature: [16][256]
    float* bps = out + BB * OUTD;          // bps_feature:    [16][16384]

    float *p1, *p2, *p3, *h1, *h2, *tmp;
    cudaGetSymbolAddress((void**)&p1, g_part1);
    cudaGetSymbolAddress((void**)&p2, g_part2);
    cudaGetSymbolAddress((void**)&p3, g_part3);
    cudaGetSymbolAddress((void**)&h1, g_h1);
    cudaGetSymbolAddress((void**)&h2, g_h2);
    cudaGetSymbolAddress((void**)&tmp, g_tmp);

    // slot shims so the 4th launch (ncu window) is k_argmin
    k_nop<<<1, 32>>>();
    k_nop<<<1, 32>>>();
    k_prep<<<(BB * NN / 2 + 255) / 256, 256>>>(pc);

    k_argmin<<<dim3(KK / (128 * QQ), NCHUNK, BB), 128>>>(basis);
    k_finish<<<(BB * KK) / 256, 256>>>(pc, basis, bps);

    // layer 1: [16,16384] @ [16384,1024] — 256 blocks, 128-way split-K
    k_gemm2c<128><<<dim3(H1 / 512, IN1 / 128), 256>>>(bps, W1, p1, IN1, H1);
    k_red_s1<8><<<(16 * BB * H1 / 4) / 256, 256>>>((const float4*)p1, (float4*)tmp, BB * H1 / 4);
    k_red_s2<16><<<(BB * H1 / 4) / 256, 256>>>((const float4*)tmp, (const float4*)b1, (float4*)h1,
                                               BB * H1 / 4, H1 / 4, 1);

    // layer 2: [16,1024] @ [1024,512] — 64 blocks, 64-way split-K
    k_gemm2c<16><<<dim3(H2 / 512, H1 / 16), 256>>>(h1, W2, p2, H1, H2);
    k_red_s1<8><<<(8 * BB * H2 / 4) / 256, 256>>>((const float4*)p2, (float4*)tmp, BB * H2 / 4);
    k_red_s2<8><<<(BB * H2 / 4 + 255) / 256, 256>>>((const float4*)tmp, (const float4*)b2, (float4*)h2,
                                                    BB * H2 / 4, H2 / 4, 1);

    // layer 3: [16,512] @ [512,256] — 16 blocks, 16-way split-K
    k_gemm1c<32><<<dim3(OUTD / 256, H2 / 32), 256>>>(h2, W3, p3, H2, OUTD);
    k_red_s2<16><<<(BB * OUTD / 4 + 255) / 256, 256>>>((const float4*)p3, (const float4*)b3, (float4*)out,
                                                       BB * OUTD / 4, OUTD / 4, 0);
}

// round 9
// speedup vs baseline: 1.0538x; 1.0538x over previous
#include <cuda_runtime.h>
#include <math.h>
#include <float.h>

#define BB   16
#define NN   4096
#define KK   4096
#define NCHUNK 8
#define CHUNK  512       // NN / NCHUNK
#define QQ   2           // queries per thread in argmin
#define IN1  16384
#define H1   1024
#define H2   512
#define OUTD 256

typedef unsigned long long ull;

#define FMA2(out, a, b, c) asm("fma.rn.f32x2 %0, %1, %2, %3;" : "=l"(out) : "l"(a), "l"(b), "l"(c))
#define MUL2(out, a, b)    asm("mul.rn.f32x2 %0, %1, %2;"     : "=l"(out) : "l"(a), "l"(b))
#define ADD2(out, a, b)    asm("add.rn.f32x2 %0, %1, %2;"     : "=l"(out) : "l"(a), "l"(b))

__device__ __forceinline__ ull pk2(float lo, float hi) {
    ull r; asm("mov.b64 %0, {%1, %2};" : "=l"(r) : "f"(lo), "f"(hi)); return r;
}
__device__ __forceinline__ void upk2(float& lo, float& hi, ull v) {
    asm("mov.b64 {%0, %1}, %2;" : "=f"(lo), "=f"(hi) : "l"(v));
}

// ---- scratch ----
__device__ __align__(16) float4 g_packA[BB * NN / 2];       // 512 KB
__device__ __align__(16) float4 g_packB[BB * NN / 2];       // 512 KB
__device__ __align__(16) float2 g_bi  [BB * KK * NCHUNK];   // 4 MB (best, idx-bits)
__device__ __align__(16) float  g_part1[128 * BB * H1];     // 8 MB
__device__ __align__(16) float  g_tmp  [16 * BB * H1];      // 1 MB
__device__ __align__(16) float  g_h1[BB * H1];
__device__ __align__(16) float  g_part2[64 * BB * H2];
__device__ __align__(16) float  g_h2[BB * H2];
__device__ __align__(16) float  g_part3[16 * BB * OUTD];
__device__ float g_dummy[32];

// ---- slot-shift no-op (deterministic) ----
__global__ void k_nop() { if (threadIdx.x == 0) g_dummy[blockIdx.x] = 1.0f; }

// ============================================================
// Prep: pack (-2x,-2y) pairs and (-2z,pn) pairs once.
//   pn = rn(rn(x*x)+rn(y*y))+rn(z*z)  (reference order)
// ============================================================
__global__ void k_prep(const float* __restrict__ pc) {
    const int t = blockIdx.x * 256 + threadIdx.x;     // over BB*NN/2
    if (t >= BB * NN / 2) return;
    const float* p = pc + (size_t)t * 6;
    float x0 = p[0], y0 = p[1], z0 = p[2];
    float x1 = p[3], y1 = p[4], z1 = p[5];
    float pn0 = __fadd_rn(__fadd_rn(__fmul_rn(x0, x0), __fmul_rn(y0, y0)),
                          __fmul_rn(z0, z0));
    float pn1 = __fadd_rn(__fadd_rn(__fmul_rn(x1, x1), __fmul_rn(y1, y1)),
                          __fmul_rn(z1, z1));
    g_packA[t] = make_float4(-2.0f * x0, -2.0f * x1, -2.0f * y0, -2.0f * y1);
    g_packB[t] = make_float4(-2.0f * z0, -2.0f * z1, pn0, pn1);
}

// shared tiles for argmin
struct ArgminSmem {
    ulonglong2 spA[CHUNK / 2];
    ulonglong2 spB[CHUNK / 2];
};

// recompute scalar distances inside winning group, first index == best
__device__ __forceinline__ int resolve_group(const ArgminSmem* s, int bg, float best,
                                             float bx, float by, float bz, float bn) {
    int bi = 0;
    bool found = false;
    #pragma unroll
    for (int p = 0; p < 4; p++) {
        ulonglong2 qa = s->spA[4 * bg + p];
        ulonglong2 qb = s->spB[4 * bg + p];
        float m2x0, m2x1, m2y0, m2y1, m2z0, m2z1, pn0, pn1;
        upk2(m2x0, m2x1, qa.x);
        upk2(m2y0, m2y1, qa.y);
        upk2(m2z0, m2z1, qb.x);
        upk2(pn0,  pn1,  qb.y);
        float c0 = __fmaf_rn(bz, m2z0, __fmaf_rn(by, m2y0, __fmul_rn(bx, m2x0)));
        float d0 = __fadd_rn(c0, __fadd_rn(bn, pn0));
        float c1 = __fmaf_rn(bz, m2z1, __fmaf_rn(by, m2y1, __fmul_rn(bx, m2x1)));
        float d1 = __fadd_rn(c1, __fadd_rn(bn, pn1));
        if (!found && d0 == best) { bi = 8 * bg + 2 * p;     found = true; }
        if (!found && d1 == best) { bi = 8 * bg + 2 * p + 1; found = true; }
    }
    return bi;
}

// ============================================================
// Argmin: bit-exact reference arithmetic, 2 pts per f32x2 op,
// 2 queries/thread, group-of-8 deferred min.
// NCHUNK=8 -> 2048 blocks x 128 thr = 8192 warps (occupancy!).
//   d = rn(fma(bz,-2z,fma(by,-2y,rn(bx*-2x))) + rn(bn+pn))
// grid: (KK/(128*QQ), NCHUNK, BB) = (16,8,16), block 128
// ============================================================
__global__ void __launch_bounds__(128) k_argmin(const float* __restrict__ basis) {
    __shared__ ArgminSmem s;
    const int b  = blockIdx.z;
    const int c  = blockIdx.y;
    const int n0 = c * CHUNK;

    {
        const float4* srcA = g_packA + (size_t)b * (NN / 2) + c * (CHUNK / 2);
        const float4* srcB = g_packB + (size_t)b * (NN / 2) + c * (CHUNK / 2);
        float4* dA = (float4*)s.spA;
        float4* dB = (float4*)s.spB;
        #pragma unroll
        for (int j = threadIdx.x; j < CHUNK / 2; j += 128) {
            dA[j] = srcA[j];
            dB[j] = srcB[j];
        }
    }
    __syncthreads();

    const int k1 = blockIdx.x * 128 + threadIdx.x;    // 0..2047
    const int k2 = k1 + KK / QQ;                      // +2048

    const float bx1 = basis[k1 * 3 + 0], by1 = basis[k1 * 3 + 1], bz1 = basis[k1 * 3 + 2];
    const float bx2 = basis[k2 * 3 + 0], by2 = basis[k2 * 3 + 1], bz2 = basis[k2 * 3 + 2];
    const float bn1 = __fadd_rn(__fadd_rn(__fmul_rn(bx1, bx1), __fmul_rn(by1, by1)),
                                __fmul_rn(bz1, bz1));
    const float bn2 = __fadd_rn(__fadd_rn(__fmul_rn(bx2, bx2), __fmul_rn(by2, by2)),
                                __fmul_rn(bz2, bz2));
    const ull bxp1 = pk2(bx1, bx1), byp1 = pk2(by1, by1), bzp1 = pk2(bz1, bz1), bnp1 = pk2(bn1, bn1);
    const ull bxp2 = pk2(bx2, bx2), byp2 = pk2(by2, by2), bzp2 = pk2(bz2, bz2), bnp2 = pk2(bn2, bn2);

    float best1 = FLT_MAX, best2 = FLT_MAX;
    int   bg1 = 0, bg2 = 0;

    #pragma unroll 2
    for (int g = 0; g < CHUNK / 8; g++) {
        ull e1[4], e2[4];
        #pragma unroll
        for (int p = 0; p < 4; p++) {
            ulonglong2 qa = s.spA[4 * g + p];
            ulonglong2 qb = s.spB[4 * g + p];
            ull cr, t;
            MUL2(cr, bxp1, qa.x); FMA2(cr, byp1, qa.y, cr); FMA2(cr, bzp1, qb.x, cr);
            ADD2(t, bnp1, qb.y);  ADD2(e1[p], cr, t);
            MUL2(cr, bxp2, qa.x); FMA2(cr, byp2, qa.y, cr); FMA2(cr, bzp2, qb.x, cr);
            ADD2(t, bnp2, qb.y);  ADD2(e2[p], cr, t);
        }
        {
            float a0, a1, b0, b1, c0, c1, d0, d1;
            upk2(a0, a1, e1[0]); upk2(b0, b1, e1[1]);
            upk2(c0, c1, e1[2]); upk2(d0, d1, e1[3]);
            float m8 = fminf(fminf(fminf(a0, a1), fminf(b0, b1)),
                             fminf(fminf(c0, c1), fminf(d0, d1)));
            bg1   = (m8 < best1) ? g : bg1;
            best1 = fminf(best1, m8);
        }
        {
            float a0, a1, b0, b1, c0, c1, d0, d1;
            upk2(a0, a1, e2[0]); upk2(b0, b1, e2[1]);
            upk2(c0, c1, e2[2]); upk2(d0, d1, e2[3]);
            float m8 = fminf(fminf(fminf(a0, a1), fminf(b0, b1)),
                             fminf(fminf(c0, c1), fminf(d0, d1)));
            bg2   = (m8 < best2) ? g : bg2;
            best2 = fminf(best2, m8);
        }
    }

    const int bi1 = resolve_group(&s, bg1, best1, bx1, by1, bz1, bn1);
    const int bi2 = resolve_group(&s, bg2, best2, bx2, by2, bz2, bn2);

    g_bi[(b * KK + k1) * NCHUNK + c] = make_float2(best1, __int_as_float(n0 + bi1));
    g_bi[(b * KK + k2) * NCHUNK + c] = make_float2(best2, __int_as_float(n0 + bi2));
}

// ============================================================
// Combine 8 chunk partials (ascending order, strict <), gather,
// write bps row: [dists(4096) | deltas(3*4096)]
// ============================================================
__global__ void k_finish(const float* __restrict__ pc,
                         const float* __restrict__ basis,
                         float* __restrict__ out_bps) {
    const int t = blockIdx.x * blockDim.x + threadIdx.x;
    if (t >= BB * KK) return;
    const int b = t >> 12;
    const int k = t & (KK - 1);

    const float4* q = (const float4*)(g_bi + (size_t)t * NCHUNK);
    float4 v[NCHUNK / 2];
    #pragma unroll
    for (int i = 0; i < NCHUNK / 2; i++) v[i] = q[i];

    float best = v[0].x;
    int   bi   = __float_as_int(v[0].y);
    #pragma unroll
    for (int i = 0; i < NCHUNK / 2; i++) {
        if (i > 0 && v[i].x < best) { best = v[i].x; bi = __float_as_int(v[i].y); }
        if (v[i].z < best)          { best = v[i].z; bi = __float_as_int(v[i].w); }
    }

    const float* p = pc + ((size_t)b * NN + bi) * 3;
    const float dx = __fadd_rn(p[0], -basis[k * 3 + 0]);
    const float dy = __fadd_rn(p[1], -basis[k * 3 + 1]);
    const float dz = __fadd_rn(p[2], -basis[k * 3 + 2]);
    const float ss = __fadd_rn(__fadd_rn(__fmul_rn(dx, dx), __fmul_rn(dy, dy)),
                               __fmul_rn(dz, dz));
    const float dist = sqrtf(ss);

    float* row = out_bps + (size_t)b * IN1;
    row[k]              = dist;
    row[KK + 3 * k + 0] = dx;
    row[KK + 3 * k + 1] = dy;
    row[KK + 3 * k + 2] = dz;
}

// ============================================================
// Split-K GEMM, 2 cols/thread, f32x2 acc. grid (H/512, INsz/CI)
// ============================================================
template <int CI>
__global__ void k_gemm2c(const float* __restrict__ A,
                         const float* __restrict__ W,
                         float* __restrict__ part,
                         int INsz, int H) {
    __shared__ __align__(16) float sA[CI * 16];
    const int i0 = blockIdx.y * CI;

    for (int idx = threadIdx.x; idx < CI * 16; idx += 256) {
        const int m  = idx / CI;
        const int il = idx % CI;
        sA[il * 16 + m] = A[(size_t)m * INsz + i0 + il];
    }
    __syncthreads();

    const int j = blockIdx.x * 512 + threadIdx.x;
    ull acc[16];
    #pragma unroll
    for (int m = 0; m < 16; m++) acc[m] = 0ull;

    const float* wp = W + (size_t)i0 * H + j;
    #pragma unroll 4
    for (int il = 0; il < CI; il++) {
        const float wa = wp[0];
        const float wb = wp[256];
        wp += H;
        const ull wpa = pk2(wa, wa);
        const ull wpb = pk2(wb, wb);
        const ulonglong2* ap = (const ulonglong2*)(sA + il * 16);
        ulonglong2 a0 = ap[0], a1 = ap[1], a2 = ap[2], a3 = ap[3];
        FMA2(acc[0],  a0.x, wpa, acc[0]);
        FMA2(acc[1],  a0.y, wpa, acc[1]);
        FMA2(acc[2],  a1.x, wpa, acc[2]);
        FMA2(acc[3],  a1.y, wpa, acc[3]);
        FMA2(acc[4],  a2.x, wpa, acc[4]);
        FMA2(acc[5],  a2.y, wpa, acc[5]);
        FMA2(acc[6],  a3.x, wpa, acc[6]);
        FMA2(acc[7],  a3.y, wpa, acc[7]);
        FMA2(acc[8],  a0.x, wpb, acc[8]);
        FMA2(acc[9],  a0.y, wpb, acc[9]);
        FMA2(acc[10], a1.x, wpb, acc[10]);
        FMA2(acc[11], a1.y, wpb, acc[11]);
        FMA2(acc[12], a2.x, wpb, acc[12]);
        FMA2(acc[13], a2.y, wpb, acc[13]);
        FMA2(acc[14], a3.x, wpb, acc[14]);
        FMA2(acc[15], a3.y, wpb, acc[15]);
    }

    float* pp = part + ((size_t)blockIdx.y * 16) * H + j;
    #pragma unroll
    for (int t = 0; t < 8; t++) {
        float lo, hi;
        upk2(lo, hi, acc[t]);
        pp[(size_t)(2 * t)     * H] = lo;
        pp[(size_t)(2 * t + 1) * H] = hi;
        upk2(lo, hi, acc[8 + t]);
        pp[(size_t)(2 * t)     * H + 256] = lo;
        pp[(size_t)(2 * t + 1) * H + 256] = hi;
    }
}

// ============================================================
// Split-K GEMM, 1 col/thread (H=256 tail). grid (H/256, INsz/CI)
// ============================================================
template <int CI>
__global__ void k_gemm1c(const float* __restrict__ A,
                         const float* __restrict__ W,
                         float* __restrict__ part,
                         int INsz, int H) {
    __shared__ __align__(16) float sA[CI * 16];
    const int i0 = blockIdx.y * CI;

    for (int idx = threadIdx.x; idx < CI * 16; idx += 256) {
        const int m  = idx / CI;
        const int il = idx % CI;
        sA[il * 16 + m] = A[(size_t)m * INsz + i0 + il];
    }
    __syncthreads();

    const int j = blockIdx.x * 256 + threadIdx.x;
    ull acc[8];
    #pragma unroll
    for (int m = 0; m < 8; m++) acc[m] = 0ull;

    const float* wp = W + (size_t)i0 * H + j;
    #pragma unroll 4
    for (int il = 0; il < CI; il++) {
        const float w = *wp;
        wp += H;
        const ull wpk = pk2(w, w);
        const ulonglong2* ap = (const ulonglong2*)(sA + il * 16);
        ulonglong2 a0 = ap[0], a1 = ap[1], a2 = ap[2], a3 = ap[3];
        FMA2(acc[0], a0.x, wpk, acc[0]);
        FMA2(acc[1], a0.y, wpk, acc[1]);
        FMA2(acc[2], a1.x, wpk, acc[2]);
        FMA2(acc[3], a1.y, wpk, acc[3]);
        FMA2(acc[4], a2.x, wpk, acc[4]);
        FMA2(acc[5], a2.y, wpk, acc[5]);
        FMA2(acc[6], a3.x, wpk, acc[6]);
        FMA2(acc[7], a3.y, wpk, acc[7]);
    }

    float* pp = part + ((size_t)blockIdx.y * 16) * H + j;
    #pragma unroll
    for (int t = 0; t < 8; t++) {
        float lo, hi;
        upk2(lo, hi, acc[t]);
        pp[(size_t)(2 * t)     * H] = lo;
        pp[(size_t)(2 * t + 1) * H] = hi;
    }
}

// ============================================================
// Reduces with explicit load arrays (force MLP). Ascending order.
// ============================================================
template <int P>
__global__ void __launch_bounds__(256) k_red_s1(const float4* __restrict__ part,
                                                float4* __restrict__ tmp,
                                                int total4) {
    const int t = blockIdx.x * 256 + threadIdx.x;
    const int group = t / total4;
    const int el    = t - group * total4;
    const float4* p = part + (size_t)group * P * total4 + el;
    float4 v[P];
    #pragma unroll
    for (int q = 0; q < P; q++) v[q] = p[(size_t)q * total4];
    float4 s = v[0];
    #pragma unroll
    for (int q = 1; q < P; q++) {
        s.x += v[q].x; s.y += v[q].y; s.z += v[q].z; s.w += v[q].w;
    }
    tmp[t] = s;
}

template <int NG>
__global__ void __launch_bounds__(256) k_red_s2(const float4* __restrict__ tmp,
                                                const float4* __restrict__ bias,
                                                float4* __restrict__ outv,
                                                int total4, int H4, int do_lrelu) {
    const int t = blockIdx.x * 256 + threadIdx.x;
    if (t >= total4) return;
    float4 v[NG];
    #pragma unroll
    for (int g = 0; g < NG; g++) v[g] = tmp[(size_t)g * total4 + t];
    float4 s = v[0];
    #pragma unroll
    for (int g = 1; g < NG; g++) {
        s.x += v[g].x; s.y += v[g].y; s.z += v[g].z; s.w += v[g].w;
    }
    float4 bv = bias[t & (H4 - 1)];
    s.x += bv.x; s.y += bv.y; s.z += bv.z; s.w += bv.w;
    if (do_lrelu) {
        if (s.x < 0.f) s.x *= 0.2f;
        if (s.y < 0.f) s.y *= 0.2f;
        if (s.z < 0.f) s.z *= 0.2f;
        if (s.w < 0.f) s.w *= 0.2f;
    }
    outv[t] = s;
}

// ============================================================
extern "C" void kernel_launch(void* const* d_in, const int* in_sizes, int n_in,
                              void* d_out, int out_size) {
    const float* pc    = (const float*)d_in[0];
    const float* basis = (const float*)d_in[1];
    const float* W1    = (const float*)d_in[2];
    const float* b1    = (const float*)d_in[3];
    const float* W2    = (const float*)d_in[4];
    const float* b2    = (const float*)d_in[5];
    const float* W3    = (const float*)d_in[6];
    const float* b3    = (const float*)d_in[7];

    float* out = (float*)d_out;            // global_feature: [16][256]
    float* bps = out + BB * OUTD;          // bps_feature:    [16][16384]

    float *p1, *p2, *p3, *h1, *h2, *tmp;
    cudaGetSymbolAddress((void**)&p1, g_part1);
    cudaGetSymbolAddress((void**)&p2, g_part2);
    cudaGetSymbolAddress((void**)&p3, g_part3);
    cudaGetSymbolAddress((void**)&h1, g_h1);
    cudaGetSymbolAddress((void**)&h2, g_h2);
    cudaGetSymbolAddress((void**)&tmp, g_tmp);

    // slot shims so the 4th launch (ncu window) is k_argmin
    k_nop<<<1, 32>>>();
    k_nop<<<1, 32>>>();
    k_prep<<<(BB * NN / 2 + 255) / 256, 256>>>(pc);

    k_argmin<<<dim3(KK / (128 * QQ), NCHUNK, BB), 128>>>(basis);
    k_finish<<<(BB * KK) / 256, 256>>>(pc, basis, bps);

    // layer 1: [16,16384] @ [16384,1024] — 256 blocks, 128-way split-K
    k_gemm2c<128><<<dim3(H1 / 512, IN1 / 128), 256>>>(bps, W1, p1, IN1, H1);
    k_red_s1<8><<<(16 * BB * H1 / 4) / 256, 256>>>((const float4*)p1, (float4*)tmp, BB * H1 / 4);
    k_red_s2<16><<<(BB * H1 / 4) / 256, 256>>>((const float4*)tmp, (const float4*)b1, (float4*)h1,
                                               BB * H1 / 4, H1 / 4, 1);

    // layer 2: [16,1024] @ [1024,512] — 64 blocks, 64-way split-K
    k_gemm2c<16><<<dim3(H2 / 512, H1 / 16), 256>>>(h1, W2, p2, H1, H2);
    k_red_s1<8><<<(8 * BB * H2 / 4) / 256, 256>>>((const float4*)p2, (float4*)tmp, BB * H2 / 4);
    k_red_s2<8><<<(BB * H2 / 4 + 255) / 256, 256>>>((const float4*)tmp, (const float4*)b2, (float4*)h2,
                                                    BB * H2 / 4, H2 / 4, 1);

    // layer 3: [16,512] @ [512,256] — 16 blocks, 16-way split-K
    k_gemm1c<32><<<dim3(OUTD / 256, H2 / 32), 256>>>(h2, W3, p3, H2, OUTD);
    k_red_s2<16><<<(BB * OUTD / 4 + 255) / 256, 256>>>((const float4*)p3, (const float4*)b3, (float4*)out,
                                                       BB * OUTD / 4, OUTD / 4, 0);
}

// round 10
// speedup vs baseline: 1.0663x; 1.0119x over previous
#include <cuda_runtime.h>
#include <math.h>
#include <float.h>

#define BB   16
#define NN   4096
#define KK   4096
#define NCHUNK 8
#define CHUNK  512       // NN / NCHUNK
#define QQ   4           // queries per thread in argmin
#define IN1  16384
#define H1   1024
#define H2   512
#define OUTD 256

typedef unsigned long long ull;

#define FMA2(out, a, b, c) asm("fma.rn.f32x2 %0, %1, %2, %3;" : "=l"(out) : "l"(a), "l"(b), "l"(c))
#define MUL2(out, a, b)    asm("mul.rn.f32x2 %0, %1, %2;"     : "=l"(out) : "l"(a), "l"(b))
#define ADD2(out, a, b)    asm("add.rn.f32x2 %0, %1, %2;"     : "=l"(out) : "l"(a), "l"(b))

__device__ __forceinline__ ull pk2(float lo, float hi) {
    ull r; asm("mov.b64 %0, {%1, %2};" : "=l"(r) : "f"(lo), "f"(hi)); return r;
}
__device__ __forceinline__ void upk2(float& lo, float& hi, ull v) {
    asm("mov.b64 {%0, %1}, %2;" : "=f"(lo), "=f"(hi) : "l"(v));
}

// ---- scratch ----
__device__ __align__(16) float4 g_packA[BB * NN / 2];       // 512 KB
__device__ __align__(16) float4 g_packB[BB * NN / 2];       // 512 KB
__device__ __align__(16) float2 g_bi  [BB * KK * NCHUNK];   // 4 MB (best, idx-bits)
__device__ __align__(16) float  g_part1[128 * BB * H1];     // 8 MB
__device__ __align__(16) float  g_tmp  [16 * BB * H1];      // 1 MB
__device__ __align__(16) float  g_part2[64 * BB * H2];
__device__ __align__(16) float  g_part3[16 * BB * OUTD];
__device__ float g_dummy[32];

// ---- slot-shift no-op (keeps k_argmin in the profiled slot) ----
__global__ void k_nop() { if (threadIdx.x == 0) g_dummy[blockIdx.x] = 1.0f; }

// ============================================================
// Prep: pack (-2x,-2y) pairs and (-2z,pn) pairs once.
//   pn = rn(rn(x*x)+rn(y*y))+rn(z*z)  (reference order)
// ============================================================
__global__ void k_prep(const float* __restrict__ pc) {
    const int t = blockIdx.x * 256 + threadIdx.x;     // over BB*NN/2
    if (t >= BB * NN / 2) return;
    const float* p = pc + (size_t)t * 6;
    float x0 = p[0], y0 = p[1], z0 = p[2];
    float x1 = p[3], y1 = p[4], z1 = p[5];
    float pn0 = __fadd_rn(__fadd_rn(__fmul_rn(x0, x0), __fmul_rn(y0, y0)),
                          __fmul_rn(z0, z0));
    float pn1 = __fadd_rn(__fadd_rn(__fmul_rn(x1, x1), __fmul_rn(y1, y1)),
                          __fmul_rn(z1, z1));
    g_packA[t] = make_float4(-2.0f * x0, -2.0f * x1, -2.0f * y0, -2.0f * y1);
    g_packB[t] = make_float4(-2.0f * z0, -2.0f * z1, pn0, pn1);
}

// shared tiles for argmin
struct ArgminSmem {
    ulonglong2 spA[CHUNK / 2];
    ulonglong2 spB[CHUNK / 2];
};

// recompute scalar distances inside winning group, first index == best
__device__ __forceinline__ int resolve_group(const ArgminSmem* s, int bg, float best,
                                             float bx, float by, float bz, float bn) {
    int bi = 0;
    bool found = false;
    #pragma unroll
    for (int p = 0; p < 4; p++) {
        ulonglong2 qa = s->spA[4 * bg + p];
        ulonglong2 qb = s->spB[4 * bg + p];
        float m2x0, m2x1, m2y0, m2y1, m2z0, m2z1, pn0, pn1;
        upk2(m2x0, m2x1, qa.x);
        upk2(m2y0, m2y1, qa.y);
        upk2(m2z0, m2z1, qb.x);
        upk2(pn0,  pn1,  qb.y);
        float c0 = __fmaf_rn(bz, m2z0, __fmaf_rn(by, m2y0, __fmul_rn(bx, m2x0)));
        float d0 = __fadd_rn(c0, __fadd_rn(bn, pn0));
        float c1 = __fmaf_rn(bz, m2z1, __fmaf_rn(by, m2y1, __fmul_rn(bx, m2x1)));
        float d1 = __fadd_rn(c1, __fadd_rn(bn, pn1));
        if (!found && d0 == best) { bi = 8 * bg + 2 * p;     found = true; }
        if (!found && d1 == best) { bi = 8 * bg + 2 * p + 1; found = true; }
    }
    return bi;
}

// ============================================================
// Argmin: bit-exact reference arithmetic, 2 pts per f32x2 op,
// 4 queries/thread (each 16B smem load feeds 4 queries),
// group-of-8 deferred min with per-pair running fold.
//   d = rn(fma(bz,-2z,fma(by,-2y,rn(bx*-2x))) + rn(bn+pn))
// grid: (KK/(128*QQ), NCHUNK, BB) = (8,8,16), block 128
// ============================================================
__global__ void __launch_bounds__(128) k_argmin(const float* __restrict__ basis) {
    __shared__ ArgminSmem s;
    const int b  = blockIdx.z;
    const int c  = blockIdx.y;
    const int n0 = c * CHUNK;

    {
        const float4* srcA = g_packA + (size_t)b * (NN / 2) + c * (CHUNK / 2);
        const float4* srcB = g_packB + (size_t)b * (NN / 2) + c * (CHUNK / 2);
        float4* dA = (float4*)s.spA;
        float4* dB = (float4*)s.spB;
        #pragma unroll
        for (int j = threadIdx.x; j < CHUNK / 2; j += 128) {
            dA[j] = srcA[j];
            dB[j] = srcB[j];
        }
    }
    __syncthreads();

    const int k0 = blockIdx.x * 128 + threadIdx.x;    // 0..1023

    ull bxp[QQ], byp[QQ], bzp[QQ], bnp[QQ];
    #pragma unroll
    for (int q = 0; q < QQ; q++) {
        const int kq = k0 + q * (KK / QQ);
        float bx = basis[kq * 3 + 0];
        float by = basis[kq * 3 + 1];
        float bz = basis[kq * 3 + 2];
        float bn = __fadd_rn(__fadd_rn(__fmul_rn(bx, bx), __fmul_rn(by, by)),
                             __fmul_rn(bz, bz));
        bxp[q] = pk2(bx, bx);
        byp[q] = pk2(by, by);
        bzp[q] = pk2(bz, bz);
        bnp[q] = pk2(bn, bn);
    }

    float best[QQ];
    int   bg[QQ];
    #pragma unroll
    for (int q = 0; q < QQ; q++) { best[q] = FLT_MAX; bg[q] = 0; }

    #pragma unroll 2
    for (int g = 0; g < CHUNK / 8; g++) {
        float m8[QQ];
        #pragma unroll
        for (int p = 0; p < 4; p++) {
            ulonglong2 qa = s.spA[4 * g + p];
            ulonglong2 qb = s.spB[4 * g + p];
            #pragma unroll
            for (int q = 0; q < QQ; q++) {
                ull cr, t, d;
                MUL2(cr, bxp[q], qa.x);
                FMA2(cr, byp[q], qa.y, cr);
                FMA2(cr, bzp[q], qb.x, cr);
                ADD2(t, bnp[q], qb.y);
                ADD2(d, cr, t);
                float d0, d1;
                upk2(d0, d1, d);
                float pm = fminf(d0, d1);
                m8[q] = (p == 0) ? pm : fminf(m8[q], pm);
            }
        }
        #pragma unroll
        for (int q = 0; q < QQ; q++) {
            bg[q]   = (m8[q] < best[q]) ? g : bg[q];   // strict < => earliest group
            best[q] = fminf(best[q], m8[q]);
        }
    }

    #pragma unroll
    for (int q = 0; q < QQ; q++) {
        float bx, by, bz, bn, hi;
        upk2(bx, hi, bxp[q]);
        upk2(by, hi, byp[q]);
        upk2(bz, hi, bzp[q]);
        upk2(bn, hi, bnp[q]);
        const int bi = resolve_group(&s, bg[q], best[q], bx, by, bz, bn);
        const int kq = k0 + q * (KK / QQ);
        g_bi[(b * KK + kq) * NCHUNK + c] = make_float2(best[q], __int_as_float(n0 + bi));
    }
}

// ============================================================
// Combine 8 chunk partials (ascending order, strict <), gather,
// write bps row: [dists(4096) | deltas(3*4096)]
// ============================================================
__global__ void k_finish(const float* __restrict__ pc,
                         const float* __restrict__ basis,
                         float* __restrict__ out_bps) {
    const int t = blockIdx.x * blockDim.x + threadIdx.x;
    if (t >= BB * KK) return;
    const int b = t >> 12;
    const int k = t & (KK - 1);

    const float4* q = (const float4*)(g_bi + (size_t)t * NCHUNK);
    float4 v[NCHUNK / 2];
    #pragma unroll
    for (int i = 0; i < NCHUNK / 2; i++) v[i] = q[i];

    float best = v[0].x;
    int   bi   = __float_as_int(v[0].y);
    #pragma unroll
    for (int i = 0; i < NCHUNK / 2; i++) {
        if (i > 0 && v[i].x < best) { best = v[i].x; bi = __float_as_int(v[i].y); }
        if (v[i].z < best)          { best = v[i].z; bi = __float_as_int(v[i].w); }
    }

    const float* p = pc + ((size_t)b * NN + bi) * 3;
    const float dx = __fadd_rn(p[0], -basis[k * 3 + 0]);
    const float dy = __fadd_rn(p[1], -basis[k * 3 + 1]);
    const float dz = __fadd_rn(p[2], -basis[k * 3 + 2]);
    const float ss = __fadd_rn(__fadd_rn(__fmul_rn(dx, dx), __fmul_rn(dy, dy)),
                               __fmul_rn(dz, dz));
    const float dist = sqrtf(ss);

    float* row = out_bps + (size_t)b * IN1;
    row[k]              = dist;
    row[KK + 3 * k + 0] = dx;
    row[KK + 3 * k + 1] = dy;
    row[KK + 3 * k + 2] = dz;
}

// ============================================================
// Layer-1 GEMM: split-K, 2 cols/thread, f32x2 acc.
// grid (H1/512, IN1/CI), block 256. part[ic][m][j].
// ============================================================
template <int CI>
__global__ void k_gemm2c(const float* __restrict__ A,
                         const float* __restrict__ W,
                         float* __restrict__ part,
                         int INsz, int H) {
    __shared__ __align__(16) float sA[CI * 16];
    const int i0 = blockIdx.y * CI;

    for (int idx = threadIdx.x; idx < CI * 16; idx += 256) {
        const int m  = idx / CI;
        const int il = idx % CI;
        sA[il * 16 + m] = A[(size_t)m * INsz + i0 + il];
    }
    __syncthreads();

    const int j = blockIdx.x * 512 + threadIdx.x;
    ull acc[16];
    #pragma unroll
    for (int m = 0; m < 16; m++) acc[m] = 0ull;

    const float* wp = W + (size_t)i0 * H + j;
    #pragma unroll 4
    for (int il = 0; il < CI; il++) {
        const float wa = wp[0];
        const float wb = wp[256];
        wp += H;
        const ull wpa = pk2(wa, wa);
        const ull wpb = pk2(wb, wb);
        const ulonglong2* ap = (const ulonglong2*)(sA + il * 16);
        ulonglong2 a0 = ap[0], a1 = ap[1], a2 = ap[2], a3 = ap[3];
        FMA2(acc[0],  a0.x, wpa, acc[0]);
        FMA2(acc[1],  a0.y, wpa, acc[1]);
        FMA2(acc[2],  a1.x, wpa, acc[2]);
        FMA2(acc[3],  a1.y, wpa, acc[3]);
        FMA2(acc[4],  a2.x, wpa, acc[4]);
        FMA2(acc[5],  a2.y, wpa, acc[5]);
        FMA2(acc[6],  a3.x, wpa, acc[6]);
        FMA2(acc[7],  a3.y, wpa, acc[7]);
        FMA2(acc[8],  a0.x, wpb, acc[8]);
        FMA2(acc[9],  a0.y, wpb, acc[9]);
        FMA2(acc[10], a1.x, wpb, acc[10]);
        FMA2(acc[11], a1.y, wpb, acc[11]);
        FMA2(acc[12], a2.x, wpb, acc[12]);
        FMA2(acc[13], a2.y, wpb, acc[13]);
        FMA2(acc[14], a3.x, wpb, acc[14]);
        FMA2(acc[15], a3.y, wpb, acc[15]);
    }

    float* pp = part + ((size_t)blockIdx.y * 16) * H + j;
    #pragma unroll
    for (int t = 0; t < 8; t++) {
        float lo, hi;
        upk2(lo, hi, acc[t]);
        pp[(size_t)(2 * t)     * H] = lo;
        pp[(size_t)(2 * t + 1) * H] = hi;
        upk2(lo, hi, acc[8 + t]);
        pp[(size_t)(2 * t)     * H + 256] = lo;
        pp[(size_t)(2 * t + 1) * H + 256] = hi;
    }
}

// ============================================================
// Layer-2 GEMM, FUSED input: A[m][i] = lrelu(sum_g tmp[g][m][i] + b1[i]).
// CI=16, grid (1, H1/16)=64 blocks, 2 cols/thread (H2=512).
// ============================================================
__global__ void k_gemm2f(const float* __restrict__ tmp1,
                         const float* __restrict__ b1v,
                         const float* __restrict__ W2,
                         float* __restrict__ part2) {
    __shared__ __align__(16) float sA[16 * 16];
    const int i0 = blockIdx.y * 16;

    for (int idx = threadIdx.x; idx < 16 * 16; idx += 256) {
        const int m  = idx / 16;
        const int il = idx % 16;
        const int i  = i0 + il;
        float sacc = 0.0f;
        #pragma unroll
        for (int g = 0; g < 16; g++)
            sacc += tmp1[(size_t)g * (BB * H1) + m * H1 + i];
        sacc += b1v[i];
        if (sacc < 0.0f) sacc *= 0.2f;
        sA[il * 16 + m] = sacc;
    }
    __syncthreads();

    const int j = threadIdx.x;
    ull acc[16];
    #pragma unroll
    for (int m = 0; m < 16; m++) acc[m] = 0ull;

    const float* wp = W2 + (size_t)i0 * H2 + j;
    #pragma unroll 4
    for (int il = 0; il < 16; il++) {
        const float wa = wp[0];
        const float wb = wp[256];
        wp += H2;
        const ull wpa = pk2(wa, wa);
        const ull wpb = pk2(wb, wb);
        const ulonglong2* ap = (const ulonglong2*)(sA + il * 16);
        ulonglong2 a0 = ap[0], a1 = ap[1], a2 = ap[2], a3 = ap[3];
        FMA2(acc[0],  a0.x, wpa, acc[0]);
        FMA2(acc[1],  a0.y, wpa, acc[1]);
        FMA2(acc[2],  a1.x, wpa, acc[2]);
        FMA2(acc[3],  a1.y, wpa, acc[3]);
        FMA2(acc[4],  a2.x, wpa, acc[4]);
        FMA2(acc[5],  a2.y, wpa, acc[5]);
        FMA2(acc[6],  a3.x, wpa, acc[6]);
        FMA2(acc[7],  a3.y, wpa, acc[7]);
        FMA2(acc[8],  a0.x, wpb, acc[8]);
        FMA2(acc[9],  a0.y, wpb, acc[9]);
        FMA2(acc[10], a1.x, wpb, acc[10]);
        FMA2(acc[11], a1.y, wpb, acc[11]);
        FMA2(acc[12], a2.x, wpb, acc[12]);
        FMA2(acc[13], a2.y, wpb, acc[13]);
        FMA2(acc[14], a3.x, wpb, acc[14]);
        FMA2(acc[15], a3.y, wpb, acc[15]);
    }

    float* pp = part2 + ((size_t)blockIdx.y * 16) * H2 + j;
    #pragma unroll
    for (int t = 0; t < 8; t++) {
        float lo, hi;
        upk2(lo, hi, acc[t]);
        pp[(size_t)(2 * t)     * H2] = lo;
        pp[(size_t)(2 * t + 1) * H2] = hi;
        upk2(lo, hi, acc[8 + t]);
        pp[(size_t)(2 * t)     * H2 + 256] = lo;
        pp[(size_t)(2 * t + 1) * H2 + 256] = hi;
    }
}

// ============================================================
// Layer-3 GEMM, FUSED input: A[m][i] = lrelu(sum_g tmp[g][m][i] + b2[i]).
// CI=32, grid (1, H2/32)=16 blocks, 1 col/thread (OUTD=256).
// ============================================================
__global__ void k_gemm3f(const float* __restrict__ tmp2,
                         const float* __restrict__ b2v,
                         const float* __restrict__ W3,
                         float* __restrict__ part3) {
    __shared__ __align__(16) float sA[32 * 16];
    const int i0 = blockIdx.y * 32;

    for (int idx = threadIdx.x; idx < 32 * 16; idx += 256) {
        const int m  = idx / 32;
        const int il = idx % 32;
        const int i  = i0 + il;
        float sacc = 0.0f;
        #pragma unroll
        for (int g = 0; g < 8; g++)
            sacc += tmp2[(size_t)g * (BB * H2) + m * H2 + i];
        sacc += b2v[i];
        if (sacc < 0.0f) sacc *= 0.2f;
        sA[il * 16 + m] = sacc;
    }
    __syncthreads();

    const int j = threadIdx.x;
    ull acc[8];
    #pragma unroll
    for (int m = 0; m < 8; m++) acc[m] = 0ull;

    const float* wp = W3 + (size_t)i0 * OUTD + j;
    #pragma unroll 4
    for (int il = 0; il < 32; il++) {
        const float w = *wp;
        wp += OUTD;
        const ull wpk = pk2(w, w);
        const ulonglong2* ap = (const ulonglong2*)(sA + il * 16);
        ulonglong2 a0 = ap[0], a1 = ap[1], a2 = ap[2], a3 = ap[3];
        FMA2(acc[0], a0.x, wpk, acc[0]);
        FMA2(acc[1], a0.y, wpk, acc[1]);
        FMA2(acc[2], a1.x, wpk, acc[2]);
        FMA2(acc[3], a1.y, wpk, acc[3]);
        FMA2(acc[4], a2.x, wpk, acc[4]);
        FMA2(acc[5], a2.y, wpk, acc[5]);
        FMA2(acc[6], a3.x, wpk, acc[6]);
        FMA2(acc[7], a3.y, wpk, acc[7]);
    }

    float* pp = part3 + ((size_t)blockIdx.y * 16) * OUTD + j;
    #pragma unroll
    for (int t = 0; t < 8; t++) {
        float lo, hi;
        upk2(lo, hi, acc[t]);
        pp[(size_t)(2 * t)     * OUTD] = lo;
        pp[(size_t)(2 * t + 1) * OUTD] = hi;
    }
}

// ============================================================
// Stage-1 reduce with explicit load arrays (force MLP). Ascending.
// ============================================================
template <int P>
__global__ void __launch_bounds__(256) k_red_s1(const float4* __restrict__ part,
                                                float4* __restrict__ tmp,
                                                int total4) {
    const int t = blockIdx.x * 256 + threadIdx.x;
    const int group = t / total4;
    const int el    = t - group * total4;
    const float4* p = part + (size_t)group * P * total4 + el;
    float4 v[P];
    #pragma unroll
    for (int q = 0; q < P; q++) v[q] = p[(size_t)q * total4];
    float4 s = v[0];
    #pragma unroll
    for (int q = 1; q < P; q++) {
        s.x += v[q].x; s.y += v[q].y; s.z += v[q].z; s.w += v[q].w;
    }
    tmp[t] = s;
}

// Final reduce: sum NG float4 partials + bias
template <int NG>
__global__ void __launch_bounds__(256) k_red_s2(const float4* __restrict__ tmp,
                                                const float4* __restrict__ bias,
                                                float4* __restrict__ outv,
                                                int total4, int H4) {
    const int t = blockIdx.x * 256 + threadIdx.x;
    if (t >= total4) return;
    float4 v[NG];
    #pragma unroll
    for (int g = 0; g < NG; g++) v[g] = tmp[(size_t)g * total4 + t];
    float4 s = v[0];
    #pragma unroll
    for (int g = 1; g < NG; g++) {
        s.x += v[g].x; s.y += v[g].y; s.z += v[g].z; s.w += v[g].w;
    }
    float4 bv = bias[t & (H4 - 1)];
    s.x += bv.x; s.y += bv.y; s.z += bv.z; s.w += bv.w;
    outv[t] = s;
}

// ============================================================
extern "C" void kernel_launch(void* const* d_in, const int* in_sizes, int n_in,
                              void* d_out, int out_size) {
    const float* pc    = (const float*)d_in[0];
    const float* basis = (const float*)d_in[1];
    const float* W1    = (const float*)d_in[2];
    const float* b1    = (const float*)d_in[3];
    const float* W2    = (const float*)d_in[4];
    const float* b2    = (const float*)d_in[5];
    const float* W3    = (const float*)d_in[6];
    const float* b3    = (const float*)d_in[7];

    float* out = (float*)d_out;            // global_feature: [16][256]
    float* bps = out + BB * OUTD;          // bps_feature:    [16][16384]

    float *p1, *p2, *p3, *tmp;
    cudaGetSymbolAddress((void**)&p1, g_part1);
    cudaGetSymbolAddress((void**)&p2, g_part2);
    cudaGetSymbolAddress((void**)&p3, g_part3);
    cudaGetSymbolAddress((void**)&tmp, g_tmp);

    // slot shims so the 4th launch (ncu window) is k_argmin
    k_nop<<<1, 32>>>();
    k_nop<<<1, 32>>>();
    k_prep<<<(BB * NN / 2 + 255) / 256, 256>>>(pc);

    k_argmin<<<dim3(KK / (128 * QQ), NCHUNK, BB), 128>>>(basis);
    k_finish<<<(BB * KK) / 256, 256>>>(pc, basis, bps);

    // layer 1: [16,16384] @ [16384,1024] — 256 blocks, 128-way split-K
    k_gemm2c<128><<<dim3(H1 / 512, IN1 / 128), 256>>>(bps, W1, p1, IN1, H1);
    k_red_s1<8><<<(16 * BB * H1 / 4) / 256, 256>>>((const float4*)p1, (float4*)tmp, BB * H1 / 4);

    // layer 2 (A = reduce16(tmp)+b1,lrelu fused): 64 blocks, 64-way split-K
    k_gemm2f<<<dim3(1, H1 / 16), 256>>>(tmp, b1, W2, p2);
    k_red_s1<8><<<(8 * BB * H2 / 4) / 256, 256>>>((const float4*)p2, (float4*)tmp, BB * H2 / 4);

    // layer 3 (A = reduce8(tmp)+b2,lrelu fused): 16 blocks, 16-way split-K
    k_gemm3f<<<dim3(1, H2 / 32), 256>>>(tmp, b2, W3, p3);
    k_red_s2<16><<<(BB * OUTD / 4 + 255) / 256, 256>>>((const float4*)p3, (const float4*)b3, (float4*)out,
                                                       BB * OUTD / 4, OUTD / 4);
}